// round 10
// baseline (speedup 1.0000x reference)
#include <cuda_runtime.h>

// ---------------- problem constants ----------------
#define T_    512
#define B_    64
#define DIN_  256
#define H_    1024
#define G4_   4096
#define DOUT_ 256

// ---------------- LSTM persistent-kernel tiling ----------------
#define NCTA  128     // CTAs; each owns NU hidden units
#define NU    8       // hidden units per CTA
#define NC    32      // gate columns per CTA (4 gates x NU)
#define KC    32      // k-chunk staged in SMEM
#define NTHR  128     // threads per CTA

// SMEM layout (floats)
#define SM_WX   (DIN_ * NC)        // 8192
#define SM_WH   (H_ * NC)          // 32768
#define SM_A    (2 * KC * B_)      // 4096 (double-buffered k-chunk of x or h)
#define SM_Z    (NC * B_)          // 2048
#define SM_C    (B_ * NU)          // 512
#define SM_BIAS (NC)               // 32
#define SMEM_FLOATS (SM_WX + SM_WH + SM_A + SM_Z + SM_C + SM_BIAS)
#define SMEM_BYTES  (SMEM_FLOATS * 4)   // 190,592 bytes

// ---------------- device scratch (no runtime allocations allowed) ----------------
__device__ float g_hs[(size_t)T_ * B_ * H_];   // [t][b][h]  (128 MB)
__device__ int   g_cnt[T_];                    // per-step completion counters

// ---------------- f32x2 helpers (ptxas never auto-fuses these) ----------------
static __device__ __forceinline__ unsigned long long pack2(float lo, float hi) {
    unsigned long long r;
    asm("mov.b64 %0, {%1, %2};" : "=l"(r) : "f"(lo), "f"(hi));
    return r;
}
static __device__ __forceinline__ unsigned long long fma2(unsigned long long a,
                                                          unsigned long long b,
                                                          unsigned long long c) {
    unsigned long long d;
    asm("fma.rn.f32x2 %0, %1, %2, %3;" : "=l"(d) : "l"(a), "l"(b), "l"(c));
    return d;
}
static __device__ __forceinline__ void unpack2(unsigned long long v, float &lo, float &hi) {
    asm("mov.b64 {%0, %1}, %2;" : "=f"(lo), "=f"(hi) : "l"(v));
}
static __device__ __forceinline__ int ld_acq(const int* p) {
    int v;
    asm volatile("ld.acquire.gpu.s32 %0, [%1];" : "=r"(v) : "l"(p) : "memory");
    return v;
}

// Stage one KC x B_ chunk (transposed: a_sh[kk][bat]) from a row-major source
// where each batch's k-values are contiguous. Each thread: bat = tid>>1,
// half = tid&1 -> 16 floats (4x float4 along k). Caller adds `bat` into dst.
static __device__ __forceinline__ void stage_chunk(const float* __restrict__ src_batrow,
                                                   float* __restrict__ dst, int half) {
    const float4* s4 = (const float4*)(src_batrow + half * 16);
    #pragma unroll
    for (int q = 0; q < 4; ++q) {
        float4 v = __ldcg(s4 + q);
        float* d = dst + (half * 16 + q * 4) * B_;
        d[0] = v.x; d[B_] = v.y; d[2 * B_] = v.z; d[3 * B_] = v.w;
    }
}

// Inner product over one staged chunk.
// Thread owns 2 adjacent gate columns (lc0, lc0+1) and 8 batches:
// pairs (2*bg + 16*p, +1) for p = 0..3  -> conflict-free LDS.64 pattern.
static __device__ __forceinline__ void compute_chunk(const float* __restrict__ Wb,
                                                     const float* __restrict__ A,
                                                     unsigned long long acc[2][4],
                                                     int lc0, int bg) {
    #pragma unroll
    for (int kk = 0; kk < KC; ++kk) {
        float2 w = *(const float2*)(Wb + kk * NC + lc0);       // LDS.64, broadcast
        unsigned long long w0 = pack2(w.x, w.x);
        unsigned long long w1 = pack2(w.y, w.y);
        const float* Ar = A + kk * B_ + 2 * bg;
        #pragma unroll
        for (int p = 0; p < 4; ++p) {
            unsigned long long hv = *(const unsigned long long*)(Ar + 16 * p);
            acc[0][p] = fma2(hv, w0, acc[0][p]);
            acc[1][p] = fma2(hv, w1, acc[1][p]);
        }
    }
}

// ==================== persistent LSTM recurrence ====================
__global__ void __launch_bounds__(NTHR, 1)
lstm_kernel(const float* __restrict__ x, const float* __restrict__ Wx,
            const float* __restrict__ Wh, const float* __restrict__ bias) {
    extern __shared__ float sm[];
    float* Wx_s = sm;                   // [DIN_][NC]
    float* Wh_s = Wx_s + SM_WX;         // [H_][NC]
    float* a_sh = Wh_s + SM_WH;         // [2][KC][B_]
    float* z_sh = a_sh + SM_A;          // [NC][B_]   (gate*NU+unit major)
    float* c_sh = z_sh + SM_Z;          // [bat*NU + unit]
    float* b_sh = c_sh + SM_C;          // [NC]

    const int tid = threadIdx.x;
    const int u0  = blockIdx.x * NU;

    // ---- one-time weight gather (column slices, gate-major local order) ----
    for (int idx = tid; idx < SM_WX; idx += NTHR) {
        int k = idx >> 5, lc = idx & 31;
        int gate = lc >> 3, unit = lc & 7;
        Wx_s[idx] = Wx[(size_t)k * G4_ + gate * H_ + u0 + unit];
    }
    for (int idx = tid; idx < SM_WH; idx += NTHR) {
        int k = idx >> 5, lc = idx & 31;
        int gate = lc >> 3, unit = lc & 7;
        Wh_s[idx] = Wh[(size_t)k * G4_ + gate * H_ + u0 + unit];
    }
    if (tid < NC) {
        int gate = tid >> 3, unit = tid & 7;
        b_sh[tid] = bias[gate * H_ + u0 + unit];
    }
    for (int idx = tid; idx < SM_C; idx += NTHR) c_sh[idx] = 0.f;
    __syncthreads();

    const int cc  = tid >> 3;      // 0..15
    const int bg  = tid & 7;       // 0..7
    const int lc0 = cc * 2;

    const int bat  = tid >> 1;     // staging role: batch 0..63
    const int half = tid & 1;      // staging role: k-half

    for (int t = 0; t < T_; ++t) {
        unsigned long long acc[2][4];
        #pragma unroll
        for (int c = 0; c < 2; ++c)
            #pragma unroll
            for (int p = 0; p < 4; ++p) acc[c][p] = 0ull;

        // ---------- phase X: 8 chunks of x_t (no dependence on h) ----------
        const float* xb = x + (size_t)bat * (T_ * DIN_) + (size_t)t * DIN_;
        stage_chunk(xb, a_sh + bat, half);
        __syncthreads();
        for (int j = 0; j < 8; ++j) {
            int cur = j & 1;
            if (j < 7)
                stage_chunk(xb + (j + 1) * KC, a_sh + (cur ^ 1) * KC * B_ + bat, half);
            compute_chunk(Wx_s + j * KC * NC, a_sh + cur * KC * B_, acc, lc0, bg);
            __syncthreads();
        }

        // ---------- phase H: wait for h_{t-1}, then 32 chunks ----------
        if (t > 0) {
            if (tid == 0) {
                while (ld_acq(&g_cnt[t - 1]) < NCTA) { __nanosleep(32); }
            }
            __syncthreads();
            const float* hb = g_hs + (size_t)(t - 1) * (B_ * H_) + (size_t)bat * H_;
            stage_chunk(hb, a_sh + bat, half);
            __syncthreads();
            for (int j = 0; j < 32; ++j) {
                int cur = j & 1;
                if (j < 31)
                    stage_chunk(hb + (j + 1) * KC, a_sh + (cur ^ 1) * KC * B_ + bat, half);
                compute_chunk(Wh_s + j * KC * NC, a_sh + cur * KC * B_, acc, lc0, bg);
                __syncthreads();
            }
        }

        // ---------- publish z (+bias) to SMEM ----------
        #pragma unroll
        for (int c = 0; c < 2; ++c) {
            float bb = b_sh[lc0 + c];
            #pragma unroll
            for (int p = 0; p < 4; ++p) {
                float lo, hi; unpack2(acc[c][p], lo, hi);
                int bb0 = 2 * bg + 16 * p;
                z_sh[(lc0 + c) * B_ + bb0]     = lo + bb;
                z_sh[(lc0 + c) * B_ + bb0 + 1] = hi + bb;
            }
        }
        __syncthreads();

        // ---------- cell update: 512 cells, 4 per thread ----------
        {
            int base = tid * 4;          // idx = bat*NU + unit
            int cb   = base >> 3;        // batch
            int un0  = base & 7;         // 0 or 4
            float hout[4];
            #pragma unroll
            for (int i = 0; i < 4; ++i) {
                int unit = un0 + i;
                float zi = z_sh[(0 * NU + unit) * B_ + cb];
                float zf = z_sh[(1 * NU + unit) * B_ + cb];
                float zg = z_sh[(2 * NU + unit) * B_ + cb];
                float zo = z_sh[(3 * NU + unit) * B_ + cb];
                float ig = 1.f / (1.f + expf(-zi));
                float fg = 1.f / (1.f + expf(-zf));
                float gg = tanhf(zg);
                float og = 1.f / (1.f + expf(-zo));
                float cv = fg * c_sh[base + i] + ig * gg;
                c_sh[base + i] = cv;
                hout[i] = og * tanhf(cv);
            }
            float4* dst = (float4*)(g_hs + (size_t)t * (B_ * H_) +
                                    (size_t)cb * H_ + u0 + un0);
            *dst = make_float4(hout[0], hout[1], hout[2], hout[3]);
        }

        // ---------- release h_t ----------
        __threadfence();
        __syncthreads();
        if (tid == 0) atomicAdd(&g_cnt[t], 1);
    }
}

// ==================== output projection: relu(hs @ Wo + bo) ====================
// One 64-row tile == one timestep (all 64 batches).
#define PBM 64
#define PBN 64
#define PBK 16

__global__ void __launch_bounds__(256, 1)
proj_kernel(const float* __restrict__ Wo, const float* __restrict__ bo,
            float* __restrict__ out) {
    __shared__ float Ash[PBK][PBM];
    __shared__ float Bsh[PBK][PBN];

    const int t  = blockIdx.x;            // 0..511
    const int n0 = blockIdx.y * PBN;      // 0 / 64 / 128 / 192
    const int tid = threadIdx.x;
    const int tx = tid & 15, ty = tid >> 4;

    const float* A = g_hs + (size_t)t * (B_ * H_);   // [64][1024]

    const int lm  = tid >> 2;             // A-load row (batch) 0..63
    const int lk4 = (tid & 3) * 4;        // A-load k sub-offset
    const int lkb = tid >> 4;             // B-load k row 0..15
    const int ln4 = (tid & 15) * 4;       // B-load n sub-offset

    unsigned long long acc2[4][2];
    #pragma unroll
    for (int i = 0; i < 4; ++i) { acc2[i][0] = 0ull; acc2[i][1] = 0ull; }

    for (int k0 = 0; k0 < H_; k0 += PBK) {
        float4 av = *(const float4*)(A + (size_t)lm * H_ + k0 + lk4);
        Ash[lk4 + 0][lm] = av.x; Ash[lk4 + 1][lm] = av.y;
        Ash[lk4 + 2][lm] = av.z; Ash[lk4 + 3][lm] = av.w;
        float4 bv = *(const float4*)(Wo + (size_t)(k0 + lkb) * DOUT_ + n0 + ln4);
        *(float4*)&Bsh[lkb][ln4] = bv;
        __syncthreads();

        #pragma unroll
        for (int kk = 0; kk < PBK; ++kk) {
            float4 a4 = *(const float4*)&Ash[kk][ty * 4];
            float4 b4 = *(const float4*)&Bsh[kk][tx * 4];
            unsigned long long bp0 = pack2(b4.x, b4.y);
            unsigned long long bp1 = pack2(b4.z, b4.w);
            float ar[4] = {a4.x, a4.y, a4.z, a4.w};
            #pragma unroll
            for (int i = 0; i < 4; ++i) {
                unsigned long long as = pack2(ar[i], ar[i]);
                acc2[i][0] = fma2(bp0, as, acc2[i][0]);
                acc2[i][1] = fma2(bp1, as, acc2[i][1]);
            }
        }
        __syncthreads();
    }

    #pragma unroll
    for (int i = 0; i < 4; ++i) {
        int b = ty * 4 + i;               // batch
        float o0, o1, o2, o3;
        unpack2(acc2[i][0], o0, o1);
        unpack2(acc2[i][1], o2, o3);
        int nb = n0 + tx * 4;
        float4 r;
        r.x = fmaxf(o0 + bo[nb + 0], 0.f);
        r.y = fmaxf(o1 + bo[nb + 1], 0.f);
        r.z = fmaxf(o2 + bo[nb + 2], 0.f);
        r.w = fmaxf(o3 + bo[nb + 3], 0.f);
        *(float4*)(out + (size_t)b * (T_ * DOUT_) + (size_t)t * DOUT_ + nb) = r;
    }
}

// ==================== per-replay flag reset ====================
__global__ void reset_kernel() {
    if (threadIdx.x < T_) g_cnt[threadIdx.x] = 0;
}

extern "C" void kernel_launch(void* const* d_in, const int* in_sizes, int n_in,
                              void* d_out, int out_size) {
    const float* x  = (const float*)d_in[0];
    const float* Wx = (const float*)d_in[1];
    const float* Wh = (const float*)d_in[2];
    const float* b  = (const float*)d_in[3];
    const float* Wo = (const float*)d_in[4];
    const float* bo = (const float*)d_in[5];
    float* out = (float*)d_out;

    cudaFuncSetAttribute(lstm_kernel, cudaFuncAttributeMaxDynamicSharedMemorySize,
                         SMEM_BYTES);

    reset_kernel<<<1, T_>>>();
    lstm_kernel<<<NCTA, NTHR, SMEM_BYTES>>>(x, Wx, Wh, b);
    proj_kernel<<<dim3(T_, DOUT_ / PBN), 256>>>(Wo, bo, out);
}

// round 12
// speedup vs baseline: 1.1721x; 1.1721x over previous
#include <cuda_runtime.h>

// ---------------- problem constants ----------------
#define T_    512
#define B_    64
#define DIN_  256
#define H_    1024
#define G4_   4096
#define DOUT_ 256

// ---------------- LSTM persistent-kernel tiling ----------------
#define NCTA  128     // CTAs; each owns NU hidden units
#define NU    8       // hidden units per CTA
#define NC    32      // gate columns per CTA (4 gates x NU)
#define KC    32      // k-chunk staged in SMEM
#define NTHR  256     // 2 warpgroups of 128
#define XCH   8       // x chunks total (DIN/KC)
#define HCH   32      // h chunks total (H/KC)
#define XCW   (XCH/2) // x chunks per warpgroup
#define HCW   (HCH/2) // h chunks per warpgroup

// SMEM layout (floats)
#define SM_WX   (DIN_ * NC)           // 8192
#define SM_WH   (H_ * NC)             // 32768
#define SM_A    (2 * 2 * KC * B_)     // 8192  (per-wg double-buffered chunk)
#define SM_Z1   (NC * B_)             // 2048  (one wg partial)
#define SM_Z    (2 * SM_Z1)           // 4096
#define SM_C    (B_ * NU)             // 512
#define SM_BIAS (NC)                  // 32
#define SMEM_FLOATS (SM_WX + SM_WH + SM_A + SM_Z + SM_C + SM_BIAS)
#define SMEM_BYTES  (SMEM_FLOATS * 4) // 215,168 bytes

// ---------------- device scratch (no runtime allocations allowed) ----------------
__device__ float g_hs[(size_t)T_ * B_ * H_];   // [t][b][h]  (128 MB)
__device__ int   g_cnt[T_];                    // per-step completion counters

// ---------------- f32x2 helpers (ptxas never auto-fuses these) ----------------
static __device__ __forceinline__ unsigned long long pack2(float lo, float hi) {
    unsigned long long r;
    asm("mov.b64 %0, {%1, %2};" : "=l"(r) : "f"(lo), "f"(hi));
    return r;
}
static __device__ __forceinline__ unsigned long long fma2(unsigned long long a,
                                                          unsigned long long b,
                                                          unsigned long long c) {
    unsigned long long d;
    asm("fma.rn.f32x2 %0, %1, %2, %3;" : "=l"(d) : "l"(a), "l"(b), "l"(c));
    return d;
}
static __device__ __forceinline__ void unpack2(unsigned long long v, float &lo, float &hi) {
    asm("mov.b64 {%0, %1}, %2;" : "=f"(lo), "=f"(hi) : "l"(v));
}
static __device__ __forceinline__ int ld_acq(const int* p) {
    int v;
    asm volatile("ld.acquire.gpu.s32 %0, [%1];" : "=r"(v) : "l"(p) : "memory");
    return v;
}
#define BARW(id) asm volatile("bar.sync %0, 128;" :: "r"(id) : "memory")

// Stage one KC x B_ chunk (transposed: a[kk][bat]) from a row-major source
// (each batch's k-values contiguous). Within a warpgroup: bat = wtid>>1,
// half = wtid&1 -> 16 floats (4x float4 along k). Caller adds `bat` into dst.
static __device__ __forceinline__ void stage_chunk(const float* __restrict__ src_batrow,
                                                   float* __restrict__ dst, int half) {
    const float4* s4 = (const float4*)(src_batrow + half * 16);
    #pragma unroll
    for (int q = 0; q < 4; ++q) {
        float4 v = __ldcg(s4 + q);
        float* d = dst + (half * 16 + q * 4) * B_;
        d[0] = v.x; d[B_] = v.y; d[2 * B_] = v.z; d[3 * B_] = v.w;
    }
}

// Inner product over one staged chunk.
// Thread owns 2 adjacent gate columns (lc0, lc0+1) and 8 batches:
// 4*bg + {0..3} and 4*bg + 32 + {0..3}  -> LDS.128, conflict-free.
static __device__ __forceinline__ void compute_chunk(const float* __restrict__ Wb,
                                                     const float* __restrict__ A,
                                                     unsigned long long acc[2][4],
                                                     int lc0, int bg4) {
    #pragma unroll
    for (int kk = 0; kk < KC; ++kk) {
        float2 w = *(const float2*)(Wb + kk * NC + lc0);       // LDS.64, broadcast
        unsigned long long w0 = pack2(w.x, w.x);
        unsigned long long w1 = pack2(w.y, w.y);
        const float* Ar = A + kk * B_ + bg4;
        ulonglong2 h0 = *(const ulonglong2*)(Ar);              // batches bg4..+3
        ulonglong2 h1 = *(const ulonglong2*)(Ar + 32);         // batches bg4+32..+35
        acc[0][0] = fma2(h0.x, w0, acc[0][0]);
        acc[0][1] = fma2(h0.y, w0, acc[0][1]);
        acc[0][2] = fma2(h1.x, w0, acc[0][2]);
        acc[0][3] = fma2(h1.y, w0, acc[0][3]);
        acc[1][0] = fma2(h0.x, w1, acc[1][0]);
        acc[1][1] = fma2(h0.y, w1, acc[1][1]);
        acc[1][2] = fma2(h1.x, w1, acc[1][2]);
        acc[1][3] = fma2(h1.y, w1, acc[1][3]);
    }
}

// ==================== persistent LSTM recurrence ====================
__global__ void __launch_bounds__(NTHR, 1)
lstm_kernel(const float* __restrict__ x, const float* __restrict__ Wx,
            const float* __restrict__ Wh, const float* __restrict__ bias) {
    extern __shared__ float sm[];
    float* Wx_s = sm;                   // [DIN_][NC]
    float* Wh_s = Wx_s + SM_WX;         // [H_][NC]
    float* a_sh = Wh_s + SM_WH;         // [wg][2][KC][B_]
    float* z_sh = a_sh + SM_A;          // [wg][NC][B_]
    float* c_sh = z_sh + SM_Z;          // [bat*NU + unit]
    float* b_sh = c_sh + SM_C;          // [NC]

    const int tid = threadIdx.x;
    const int wg   = tid >> 7;          // 0 / 1
    const int wtid = tid & 127;
    const int u0  = blockIdx.x * NU;

    // ---- one-time weight gather (column slices, gate-major local order) ----
    for (int idx = tid; idx < SM_WX; idx += NTHR) {
        int k = idx >> 5, lc = idx & 31;
        int gate = lc >> 3, unit = lc & 7;
        Wx_s[idx] = Wx[(size_t)k * G4_ + gate * H_ + u0 + unit];
    }
    for (int idx = tid; idx < SM_WH; idx += NTHR) {
        int k = idx >> 5, lc = idx & 31;
        int gate = lc >> 3, unit = lc & 7;
        Wh_s[idx] = Wh[(size_t)k * G4_ + gate * H_ + u0 + unit];
    }
    if (tid < NC) {
        int gate = tid >> 3, unit = tid & 7;
        b_sh[tid] = bias[gate * H_ + u0 + unit];
    }
    for (int idx = tid; idx < SM_C; idx += NTHR) c_sh[idx] = 0.f;
    __syncthreads();

    const int cc  = wtid >> 3;          // 0..15
    const int bg4 = (wtid & 7) * 4;     // 0,4,..,28
    const int lc0 = cc * 2;

    const int bat  = wtid >> 1;         // staging role: batch 0..63
    const int half = wtid & 1;          // staging role: k-half

    float* awg  = a_sh + wg * (2 * KC * B_);
    float* zwg  = z_sh + wg * SM_Z1;
    const int barid = wg + 1;

    for (int t = 0; t < T_; ++t) {
        unsigned long long acc[2][4];
        #pragma unroll
        for (int c = 0; c < 2; ++c)
            #pragma unroll
            for (int p = 0; p < 4; ++p) acc[c][p] = 0ull;

        // ---------- phase X: XCW chunks of x_t (no dependence on h) ----------
        const float* xb = x + (size_t)bat * (T_ * DIN_) + (size_t)t * DIN_;
        const int xc0 = wg * XCW;
        stage_chunk(xb + xc0 * KC, awg + bat, half);
        BARW(barid);
        for (int j = 0; j < XCW; ++j) {
            int cur = j & 1;
            if (j < XCW - 1)
                stage_chunk(xb + (xc0 + j + 1) * KC, awg + (cur ^ 1) * KC * B_ + bat, half);
            compute_chunk(Wx_s + (xc0 + j) * KC * NC, awg + cur * KC * B_, acc, lc0, bg4);
            BARW(barid);
        }

        // ---------- phase H: wait for h_{t-1}, then HCW chunks ----------
        if (t > 0) {
            if (tid == 0) {
                while (ld_acq(&g_cnt[t - 1]) < NCTA) { __nanosleep(32); }
            }
            __syncthreads();
            const float* hb = g_hs + (size_t)(t - 1) * (B_ * H_) + (size_t)bat * H_;
            const int hc0 = wg * HCW;
            stage_chunk(hb + hc0 * KC, awg + bat, half);
            BARW(barid);
            for (int j = 0; j < HCW; ++j) {
                int cur = j & 1;
                if (j < HCW - 1)
                    stage_chunk(hb + (hc0 + j + 1) * KC, awg + (cur ^ 1) * KC * B_ + bat, half);
                compute_chunk(Wh_s + (hc0 + j) * KC * NC, awg + cur * KC * B_, acc, lc0, bg4);
                BARW(barid);
            }
        }

        // ---------- publish partial z to this wg's buffer ----------
        #pragma unroll
        for (int c = 0; c < 2; ++c) {
            float* zrow = zwg + (lc0 + c) * B_;
            ulonglong2 v01; v01.x = acc[c][0]; v01.y = acc[c][1];
            *(ulonglong2*)(zrow + bg4) = v01;
            ulonglong2 v23; v23.x = acc[c][2]; v23.y = acc[c][3];
            *(ulonglong2*)(zrow + bg4 + 32) = v23;
        }
        __syncthreads();

        // ---------- cell update: 512 cells, 2 per thread ----------
        {
            int base = tid * 2;          // idx = bat*NU + unit
            int cb   = base >> 3;        // batch
            int un0  = base & 7;         // 0,2,4,6
            float hout[2];
            #pragma unroll
            for (int i = 0; i < 2; ++i) {
                int unit = un0 + i;
                float zi = z_sh[(0 * NU + unit) * B_ + cb]
                         + z_sh[SM_Z1 + (0 * NU + unit) * B_ + cb] + b_sh[0 * NU + unit];
                float zf = z_sh[(1 * NU + unit) * B_ + cb]
                         + z_sh[SM_Z1 + (1 * NU + unit) * B_ + cb] + b_sh[1 * NU + unit];
                float zg = z_sh[(2 * NU + unit) * B_ + cb]
                         + z_sh[SM_Z1 + (2 * NU + unit) * B_ + cb] + b_sh[2 * NU + unit];
                float zo = z_sh[(3 * NU + unit) * B_ + cb]
                         + z_sh[SM_Z1 + (3 * NU + unit) * B_ + cb] + b_sh[3 * NU + unit];
                float ig = 1.f / (1.f + expf(-zi));
                float fg = 1.f / (1.f + expf(-zf));
                float gg = tanhf(zg);
                float og = 1.f / (1.f + expf(-zo));
                float cv = fg * c_sh[base + i] + ig * gg;
                c_sh[base + i] = cv;
                hout[i] = og * tanhf(cv);
            }
            float2* dst = (float2*)(g_hs + (size_t)t * (B_ * H_) +
                                    (size_t)cb * H_ + u0 + un0);
            *dst = make_float2(hout[0], hout[1]);
        }

        // ---------- release h_t ----------
        __threadfence();
        __syncthreads();
        if (tid == 0) atomicAdd(&g_cnt[t], 1);
    }
}

// ==================== output projection: relu(hs @ Wo + bo) ====================
// One 64-row tile == one timestep (all 64 batches).
#define PBM 64
#define PBN 64
#define PBK 16

__global__ void __launch_bounds__(256, 1)
proj_kernel(const float* __restrict__ Wo, const float* __restrict__ bo,
            float* __restrict__ out) {
    __shared__ float Ash[PBK][PBM];
    __shared__ float Bsh[PBK][PBN];

    const int t  = blockIdx.x;            // 0..511
    const int n0 = blockIdx.y * PBN;      // 0 / 64 / 128 / 192
    const int tid = threadIdx.x;
    const int tx = tid & 15, ty = tid >> 4;

    const float* A = g_hs + (size_t)t * (B_ * H_);   // [64][1024]

    const int lm  = tid >> 2;             // A-load row (batch) 0..63
    const int lk4 = (tid & 3) * 4;        // A-load k sub-offset
    const int lkb = tid >> 4;             // B-load k row 0..15
    const int ln4 = (tid & 15) * 4;       // B-load n sub-offset

    unsigned long long acc2[4][2];
    #pragma unroll
    for (int i = 0; i < 4; ++i) { acc2[i][0] = 0ull; acc2[i][1] = 0ull; }

    for (int k0 = 0; k0 < H_; k0 += PBK) {
        float4 av = *(const float4*)(A + (size_t)lm * H_ + k0 + lk4);
        Ash[lk4 + 0][lm] = av.x; Ash[lk4 + 1][lm] = av.y;
        Ash[lk4 + 2][lm] = av.z; Ash[lk4 + 3][lm] = av.w;
        float4 bv = *(const float4*)(Wo + (size_t)(k0 + lkb) * DOUT_ + n0 + ln4);
        *(float4*)&Bsh[lkb][ln4] = bv;
        __syncthreads();

        #pragma unroll
        for (int kk = 0; kk < PBK; ++kk) {
            float4 a4 = *(const float4*)&Ash[kk][ty * 4];
            float4 b4 = *(const float4*)&Bsh[kk][tx * 4];
            unsigned long long bp0 = pack2(b4.x, b4.y);
            unsigned long long bp1 = pack2(b4.z, b4.w);
            float ar[4] = {a4.x, a4.y, a4.z, a4.w};
            #pragma unroll
            for (int i = 0; i < 4; ++i) {
                unsigned long long as = pack2(ar[i], ar[i]);
                acc2[i][0] = fma2(bp0, as, acc2[i][0]);
                acc2[i][1] = fma2(bp1, as, acc2[i][1]);
            }
        }
        __syncthreads();
    }

    #pragma unroll
    for (int i = 0; i < 4; ++i) {
        int b = ty * 4 + i;               // batch
        float o0, o1, o2, o3;
        unpack2(acc2[i][0], o0, o1);
        unpack2(acc2[i][1], o2, o3);
        int nb = n0 + tx * 4;
        float4 r;
        r.x = fmaxf(o0 + bo[nb + 0], 0.f);
        r.y = fmaxf(o1 + bo[nb + 1], 0.f);
        r.z = fmaxf(o2 + bo[nb + 2], 0.f);
        r.w = fmaxf(o3 + bo[nb + 3], 0.f);
        *(float4*)(out + (size_t)b * (T_ * DOUT_) + (size_t)t * DOUT_ + nb) = r;
    }
}

// ==================== per-replay flag reset ====================
__global__ void reset_kernel() {
    if (threadIdx.x < T_) g_cnt[threadIdx.x] = 0;
}

extern "C" void kernel_launch(void* const* d_in, const int* in_sizes, int n_in,
                              void* d_out, int out_size) {
    const float* x  = (const float*)d_in[0];
    const float* Wx = (const float*)d_in[1];
    const float* Wh = (const float*)d_in[2];
    const float* b  = (const float*)d_in[3];
    const float* Wo = (const float*)d_in[4];
    const float* bo = (const float*)d_in[5];
    float* out = (float*)d_out;

    cudaFuncSetAttribute(lstm_kernel, cudaFuncAttributeMaxDynamicSharedMemorySize,
                         SMEM_BYTES);

    reset_kernel<<<1, T_>>>();
    lstm_kernel<<<NCTA, NTHR, SMEM_BYTES>>>(x, Wx, Wh, b);
    proj_kernel<<<dim3(T_, DOUT_ / PBN), 256>>>(Wo, bo, out);
}

// round 13
// speedup vs baseline: 1.2006x; 1.0244x over previous
#include <cuda_runtime.h>

// ---------------- problem constants ----------------
#define T_    512
#define B_    64
#define DIN_  256
#define H_    1024
#define G4_   4096
#define DOUT_ 256

// ---------------- LSTM persistent-kernel tiling ----------------
#define NCTA  128     // CTAs; each owns NU hidden units
#define NU    8       // hidden units per CTA
#define NC    32      // gate columns per CTA (4 gates x NU)
#define KC    16      // k-chunk staged in SMEM
#define NWG   4       // warpgroups (k split 4 ways)
#define NTHR  512     // 4 warpgroups of 128
#define XCH   (DIN_/KC)   // 16 x chunks total
#define HCH   (H_/KC)     // 64 h chunks total
#define XCW   (XCH/NWG)   // 4 per wg
#define HCW   (HCH/NWG)   // 16 per wg

// SMEM layout (floats)
#define SM_WX   (DIN_ * NC)           // 8192
#define SM_WH   (H_ * NC)             // 32768
#define SM_A    (NWG * 2 * KC * B_)   // 8192  (per-wg double-buffered chunk)
#define SM_Z1   (NC * B_)             // 2048  (one wg partial)
#define SM_Z    (NWG * SM_Z1)         // 8192
#define SM_C    (B_ * NU)             // 512
#define SM_BIAS (NC)                  // 32
#define SMEM_FLOATS (SM_WX + SM_WH + SM_A + SM_Z + SM_C + SM_BIAS)
#define SMEM_BYTES  (SMEM_FLOATS * 4) // 231,552 bytes (<= 232,448 limit)

// ---------------- device scratch (no runtime allocations allowed) ----------------
__device__ float g_hs[(size_t)T_ * B_ * H_];   // [t][b][h]  (128 MB)
__device__ int   g_cnt[T_];                    // monotonic per-step counters

// ---------------- f32x2 helpers ----------------
static __device__ __forceinline__ unsigned long long pack2(float lo, float hi) {
    unsigned long long r;
    asm("mov.b64 %0, {%1, %2};" : "=l"(r) : "f"(lo), "f"(hi));
    return r;
}
static __device__ __forceinline__ unsigned long long fma2(unsigned long long a,
                                                          unsigned long long b,
                                                          unsigned long long c) {
    unsigned long long d;
    asm("fma.rn.f32x2 %0, %1, %2, %3;" : "=l"(d) : "l"(a), "l"(b), "l"(c));
    return d;
}
static __device__ __forceinline__ void unpack2(unsigned long long v, float &lo, float &hi) {
    asm("mov.b64 {%0, %1}, %2;" : "=f"(lo), "=f"(hi) : "l"(v));
}
static __device__ __forceinline__ int ld_acq(const int* p) {
    int v;
    asm volatile("ld.acquire.gpu.s32 %0, [%1];" : "=r"(v) : "l"(p) : "memory");
    return v;
}
#define BARW(id) asm volatile("bar.sync %0, 128;" :: "r"(id) : "memory")

// Stage one KC(=16) x B_ chunk (transposed: a[kk][bat]).
// Within a warpgroup: bat = wtid>>1, half = wtid&1 -> 8 floats (2x float4).
static __device__ __forceinline__ void stage16(const float* __restrict__ src,
                                               float* __restrict__ dst, int half) {
    const float4* s4 = (const float4*)(src + half * 8);
    #pragma unroll
    for (int q = 0; q < 2; ++q) {
        float4 v = __ldcg(s4 + q);
        float* d = dst + (half * 8 + q * 4) * B_;
        d[0] = v.x; d[B_] = v.y; d[2 * B_] = v.z; d[3 * B_] = v.w;
    }
}

// Inner product over one staged KC=16 chunk.
// Thread owns 2 gate columns (lc0, lc0+1) and 8 batches (bg4+{0..3}, bg4+32+{0..3}).
static __device__ __forceinline__ void compute16(const float* __restrict__ Wb,
                                                 const float* __restrict__ A,
                                                 unsigned long long acc[2][4],
                                                 int lc0, int bg4) {
    #pragma unroll
    for (int kk = 0; kk < KC; ++kk) {
        float2 w = *(const float2*)(Wb + kk * NC + lc0);   // LDS.64 broadcast
        unsigned long long w0 = pack2(w.x, w.x);
        unsigned long long w1 = pack2(w.y, w.y);
        const float* Ar = A + kk * B_ + bg4;
        ulonglong2 h0 = *(const ulonglong2*)(Ar);          // LDS.128 conflict-free
        ulonglong2 h1 = *(const ulonglong2*)(Ar + 32);
        acc[0][0] = fma2(h0.x, w0, acc[0][0]);
        acc[0][1] = fma2(h0.y, w0, acc[0][1]);
        acc[0][2] = fma2(h1.x, w0, acc[0][2]);
        acc[0][3] = fma2(h1.y, w0, acc[0][3]);
        acc[1][0] = fma2(h0.x, w1, acc[1][0]);
        acc[1][1] = fma2(h0.y, w1, acc[1][1]);
        acc[1][2] = fma2(h1.x, w1, acc[1][2]);
        acc[1][3] = fma2(h1.y, w1, acc[1][3]);
    }
}

// ==================== persistent LSTM + projection megakernel ====================
__global__ void __launch_bounds__(NTHR, 1)
mega_kernel(const float* __restrict__ x, const float* __restrict__ Wx,
            const float* __restrict__ Wh, const float* __restrict__ bias,
            const float* __restrict__ Wo, const float* __restrict__ bo,
            float* __restrict__ out) {
    extern __shared__ float sm[];
    float* Wx_s = sm;                   // [DIN_][NC]
    float* Wh_s = Wx_s + SM_WX;         // [H_][NC]
    float* a_sh = Wh_s + SM_WH;         // [wg][2][KC][B_]
    float* z_sh = a_sh + SM_A;          // [wg][NC][B_]
    float* c_sh = z_sh + SM_Z;          // [bat*NU + unit]
    float* b_sh = c_sh + SM_C;          // [NC]

    const int tid  = threadIdx.x;
    const int wg   = tid >> 7;          // 0..3
    const int wtid = tid & 127;
    const int u0   = blockIdx.x * NU;

    // epoch base: read FIRST (all g_cnt[] entries equal & stable at launch start;
    // the earliest increment this launch is >>10us away).
    int base = 0;
    if (tid == 0) base = ld_acq(&g_cnt[0]);

    // ---- one-time weight gather (column slices, gate-major local order) ----
    for (int idx = tid; idx < SM_WX; idx += NTHR) {
        int k = idx >> 5, lc = idx & 31;
        int gate = lc >> 3, unit = lc & 7;
        Wx_s[idx] = Wx[(size_t)k * G4_ + gate * H_ + u0 + unit];
    }
    for (int idx = tid; idx < SM_WH; idx += NTHR) {
        int k = idx >> 5, lc = idx & 31;
        int gate = lc >> 3, unit = lc & 7;
        Wh_s[idx] = Wh[(size_t)k * G4_ + gate * H_ + u0 + unit];
    }
    if (tid < NC) {
        int gate = tid >> 3, unit = tid & 7;
        b_sh[tid] = bias[gate * H_ + u0 + unit];
    }
    for (int idx = tid; idx < SM_C; idx += NTHR) c_sh[idx] = 0.f;
    __syncthreads();

    const int cc  = wtid >> 3;          // 0..15
    const int bg4 = (wtid & 7) * 4;     // 0,4,..,28
    const int lc0 = cc * 2;

    const int bat  = wtid >> 1;         // staging role: batch 0..63
    const int half = wtid & 1;          // staging role: k-half

    float* awg   = a_sh + wg * (2 * KC * B_);
    float* zwg   = z_sh + wg * SM_Z1;
    const int barid = wg + 1;
    const int xc0 = wg * XCW;
    const int hc0 = wg * HCW;

    for (int t = 0; t < T_; ++t) {
        unsigned long long acc[2][4];
        #pragma unroll
        for (int c = 0; c < 2; ++c)
            #pragma unroll
            for (int p = 0; p < 4; ++p) acc[c][p] = 0ull;

        // ---------- phase X: XCW chunks of x_t (no dependence on h) ----------
        const float* xb = x + (size_t)bat * (T_ * DIN_) + (size_t)t * DIN_;
        stage16(xb + xc0 * KC, awg + bat, half);
        BARW(barid);
        for (int j = 0; j < XCW; ++j) {
            int cur = j & 1;
            if (j < XCW - 1)
                stage16(xb + (xc0 + j + 1) * KC, awg + (cur ^ 1) * KC * B_ + bat, half);
            compute16(Wx_s + (xc0 + j) * KC * NC, awg + cur * KC * B_, acc, lc0, bg4);
            BARW(barid);
        }

        // ---------- phase H: wait for h_{t-1}, then HCW chunks ----------
        if (t > 0) {
            if (tid == 0) {
                while (ld_acq(&g_cnt[t - 1]) < base + NCTA) { __nanosleep(32); }
            }
            __syncthreads();
            const float* hb = g_hs + (size_t)(t - 1) * (B_ * H_) + (size_t)bat * H_;
            stage16(hb + hc0 * KC, awg + bat, half);
            BARW(barid);
            for (int j = 0; j < HCW; ++j) {
                int cur = j & 1;
                if (j < HCW - 1)
                    stage16(hb + (hc0 + j + 1) * KC, awg + (cur ^ 1) * KC * B_ + bat, half);
                compute16(Wh_s + (hc0 + j) * KC * NC, awg + cur * KC * B_, acc, lc0, bg4);
                BARW(barid);
            }
        }

        // ---------- publish partial z to this wg's buffer ----------
        #pragma unroll
        for (int c = 0; c < 2; ++c) {
            float* zrow = zwg + (lc0 + c) * B_;
            ulonglong2 v01; v01.x = acc[c][0]; v01.y = acc[c][1];
            *(ulonglong2*)(zrow + bg4) = v01;
            ulonglong2 v23; v23.x = acc[c][2]; v23.y = acc[c][3];
            *(ulonglong2*)(zrow + bg4 + 32) = v23;
        }
        __syncthreads();

        // ---------- cell update: 512 cells, 1 per thread ----------
        {
            int cb   = tid >> 3;         // batch
            int unit = tid & 7;
            float zg4[4];
            #pragma unroll
            for (int g = 0; g < 4; ++g) {
                int row = (g * NU + unit) * B_ + cb;
                float s = b_sh[g * NU + unit];
                #pragma unroll
                for (int w = 0; w < NWG; ++w) s += z_sh[w * SM_Z1 + row];
                zg4[g] = s;
            }
            float ig = 1.f / (1.f + expf(-zg4[0]));
            float fg = 1.f / (1.f + expf(-zg4[1]));
            float gg = tanhf(zg4[2]);
            float og = 1.f / (1.f + expf(-zg4[3]));
            float cv = fg * c_sh[tid] + ig * gg;
            c_sh[tid] = cv;
            g_hs[(size_t)t * (B_ * H_) + (size_t)cb * H_ + u0 + unit] = og * tanhf(cv);
        }

        // ---------- release h_t ----------
        __threadfence();
        __syncthreads();
        if (tid == 0) atomicAdd(&g_cnt[t], 1);
    }

    // ==================== projection phase: relu(hs @ Wo + bo) ====================
    // CTA i projects timesteps 4i .. 4i+3.
    const int t0p = blockIdx.x * 4;
    if (tid == 0) {
        for (int tt = 0; tt < 4; ++tt)
            while (ld_acq(&g_cnt[t0p + tt]) < base + NCTA) { __nanosleep(32); }
    }
    __syncthreads();

    float* Bsh = sm;                       // reuse SMEM: [32][DOUT_] = 32 KB
    const int bb = tid >> 3;               // batch 0..63
    const int nq = (tid & 7) * 4;          // col sub-offset; thread covers nq+32*j, j=0..7

    for (int tt = 0; tt < 4; ++tt) {
        const int t = t0p + tt;
        const float* A = g_hs + (size_t)t * (B_ * H_) + (size_t)bb * H_;
        unsigned long long acc2[8][2];
        #pragma unroll
        for (int j = 0; j < 8; ++j) { acc2[j][0] = 0ull; acc2[j][1] = 0ull; }

        for (int k0 = 0; k0 < H_; k0 += 32) {
            // stage Wo[k0:k0+32, :] into Bsh (coalesced, 16 floats/thread)
            {
                int kk = tid >> 4, n0s = (tid & 15) * 16;
                const float4* wsrc = (const float4*)(Wo + (size_t)(k0 + kk) * DOUT_ + n0s);
                float4* wdst = (float4*)(Bsh + kk * DOUT_ + n0s);
                #pragma unroll
                for (int q = 0; q < 4; ++q) wdst[q] = __ldcg(wsrc + q);
            }
            __syncthreads();

            float4 a4[8];
            const float4* ap = (const float4*)(A + k0);
            #pragma unroll
            for (int q = 0; q < 8; ++q) a4[q] = ap[q];

            #pragma unroll
            for (int kk = 0; kk < 32; ++kk) {
                float av = ((const float*)a4)[kk];
                unsigned long long aa = pack2(av, av);
                const float* wr = Bsh + kk * DOUT_ + nq;
                #pragma unroll
                for (int j = 0; j < 8; ++j) {
                    ulonglong2 w2 = *(const ulonglong2*)(wr + 32 * j);   // conflict-free
                    acc2[j][0] = fma2(w2.x, aa, acc2[j][0]);
                    acc2[j][1] = fma2(w2.y, aa, acc2[j][1]);
                }
            }
            __syncthreads();
        }

        float* orow = out + (size_t)bb * (T_ * DOUT_) + (size_t)t * DOUT_;
        #pragma unroll
        for (int j = 0; j < 8; ++j) {
            int n = nq + 32 * j;
            float o0, o1, o2, o3;
            unpack2(acc2[j][0], o0, o1);
            unpack2(acc2[j][1], o2, o3);
            float4 r;
            r.x = fmaxf(o0 + bo[n + 0], 0.f);
            r.y = fmaxf(o1 + bo[n + 1], 0.f);
            r.z = fmaxf(o2 + bo[n + 2], 0.f);
            r.w = fmaxf(o3 + bo[n + 3], 0.f);
            *(float4*)(orow + n) = r;
        }
    }
}

extern "C" void kernel_launch(void* const* d_in, const int* in_sizes, int n_in,
                              void* d_out, int out_size) {
    const float* x  = (const float*)d_in[0];
    const float* Wx = (const float*)d_in[1];
    const float* Wh = (const float*)d_in[2];
    const float* b  = (const float*)d_in[3];
    const float* Wo = (const float*)d_in[4];
    const float* bo = (const float*)d_in[5];
    float* out = (float*)d_out;

    cudaFuncSetAttribute(mega_kernel, cudaFuncAttributeMaxDynamicSharedMemorySize,
                         SMEM_BYTES);
    mega_kernel<<<NCTA, NTHR, SMEM_BYTES>>>(x, Wx, Wh, b, Wo, bo, out);
}

// round 14
// speedup vs baseline: 1.4270x; 1.1886x over previous
#include <cuda_runtime.h>

// ---------------- problem constants ----------------
#define T_    512
#define B_    64
#define DIN_  256
#define H_    1024
#define G4_   4096
#define DOUT_ 256

// ---------------- LSTM persistent-kernel tiling ----------------
#define NCTA  128     // CTAs; each owns NU hidden units
#define NU    8       // hidden units per CTA
#define NC    32      // gate columns per CTA (4 gates x NU)
#define KC    16      // k-chunk staged in SMEM
#define NWG   4       // warpgroups (k split 4 ways)
#define NTHR  512     // 4 warpgroups of 128
#define XCH   (DIN_/KC)   // 16 x chunks total
#define HCH   (H_/KC)     // 64 h chunks total
#define XCW   (XCH/NWG)   // 4 per wg
#define HCW   (HCH/NWG)   // 16 per wg

// SMEM layout (floats)
#define SM_WX   (DIN_ * NC)           // 8192
#define SM_WH   (H_ * NC)             // 32768
#define SM_A    (NWG * 2 * KC * B_)   // 8192  (per-wg double-buffered chunk)
#define SM_Z1   (NC * B_)             // 2048  (one wg partial)
#define SM_Z    (NWG * SM_Z1)         // 8192
#define SM_C    (B_ * NU)             // 512
#define SM_BIAS (NC)                  // 32
#define SMEM_FLOATS (SM_WX + SM_WH + SM_A + SM_Z + SM_C + SM_BIAS)
#define SMEM_BYTES  (SMEM_FLOATS * 4) // 231,552 bytes (<= 232,448 limit)

// ---------------- device scratch (no runtime allocations allowed) ----------------
__device__ float g_hs[(size_t)T_ * B_ * H_];   // [t][b][h]  (128 MB)
__device__ int   g_cnt[T_];                    // monotonic per-step counters

// ---------------- f32x2 helpers ----------------
static __device__ __forceinline__ unsigned long long pack2(float lo, float hi) {
    unsigned long long r;
    asm("mov.b64 %0, {%1, %2};" : "=l"(r) : "f"(lo), "f"(hi));
    return r;
}
static __device__ __forceinline__ unsigned long long fma2(unsigned long long a,
                                                          unsigned long long b,
                                                          unsigned long long c) {
    unsigned long long d;
    asm("fma.rn.f32x2 %0, %1, %2, %3;" : "=l"(d) : "l"(a), "l"(b), "l"(c));
    return d;
}
static __device__ __forceinline__ void unpack2(unsigned long long v, float &lo, float &hi) {
    asm("mov.b64 {%0, %1}, %2;" : "=f"(lo), "=f"(hi) : "l"(v));
}
static __device__ __forceinline__ int ld_acq(const int* p) {
    int v;
    asm volatile("ld.acquire.gpu.s32 %0, [%1];" : "=r"(v) : "l"(p) : "memory");
    return v;
}
#define BARW(id) asm volatile("bar.sync %0, 128;" :: "r"(id) : "memory")

// Stage one KC(=16) x B_ chunk (transposed: a[kk][bat]).
// Within a warpgroup: bat = wtid>>1, half = wtid&1 -> 8 floats (2x float4).
static __device__ __forceinline__ void stage16(const float* __restrict__ src,
                                               float* __restrict__ dst, int half) {
    const float4* s4 = (const float4*)(src + half * 8);
    #pragma unroll
    for (int q = 0; q < 2; ++q) {
        float4 v = __ldcg(s4 + q);
        float* d = dst + (half * 8 + q * 4) * B_;
        d[0] = v.x; d[B_] = v.y; d[2 * B_] = v.z; d[3 * B_] = v.w;
    }
}

// Inner product over one staged KC=16 chunk.
// Thread owns a 4x4 tile: gate columns lc0..lc0+3 and batches bat0..bat0+3.
// Per kk: 1x LDS.128 (weights, 2-address broadcast) + 1x LDS.128 (batches,
// conflict-free) -> 32 B of SMEM per 32 FMA (was 40 B per 16 FMA).
static __device__ __forceinline__ void compute16(const float* __restrict__ Wb,
                                                 const float* __restrict__ A,
                                                 unsigned long long acc[4][2],
                                                 int lc0, int bat0) {
    #pragma unroll
    for (int kk = 0; kk < KC; ++kk) {
        float4 w = *(const float4*)(Wb + kk * NC + lc0);       // LDS.128
        unsigned long long w0 = pack2(w.x, w.x);
        unsigned long long w1 = pack2(w.y, w.y);
        unsigned long long w2 = pack2(w.z, w.z);
        unsigned long long w3 = pack2(w.w, w.w);
        ulonglong2 a2 = *(const ulonglong2*)(A + kk * B_ + bat0);  // LDS.128
        acc[0][0] = fma2(a2.x, w0, acc[0][0]);
        acc[0][1] = fma2(a2.y, w0, acc[0][1]);
        acc[1][0] = fma2(a2.x, w1, acc[1][0]);
        acc[1][1] = fma2(a2.y, w1, acc[1][1]);
        acc[2][0] = fma2(a2.x, w2, acc[2][0]);
        acc[2][1] = fma2(a2.y, w2, acc[2][1]);
        acc[3][0] = fma2(a2.x, w3, acc[3][0]);
        acc[3][1] = fma2(a2.y, w3, acc[3][1]);
    }
}

// ==================== persistent LSTM + projection megakernel ====================
__global__ void __launch_bounds__(NTHR, 1)
mega_kernel(const float* __restrict__ x, const float* __restrict__ Wx,
            const float* __restrict__ Wh, const float* __restrict__ bias,
            const float* __restrict__ Wo, const float* __restrict__ bo,
            float* __restrict__ out) {
    extern __shared__ float sm[];
    float* Wx_s = sm;                   // [DIN_][NC]
    float* Wh_s = Wx_s + SM_WX;         // [H_][NC]
    float* a_sh = Wh_s + SM_WH;         // [wg][2][KC][B_]
    float* z_sh = a_sh + SM_A;          // [wg][NC][B_]
    float* c_sh = z_sh + SM_Z;          // [bat*NU + unit]
    float* b_sh = c_sh + SM_C;          // [NC]

    const int tid  = threadIdx.x;
    const int wg   = tid >> 7;          // 0..3
    const int wtid = tid & 127;
    const int u0   = blockIdx.x * NU;

    // epoch base: read FIRST (all g_cnt[] entries equal & stable at launch start;
    // the earliest increment this launch is >>10us away).
    int base = 0;
    if (tid == 0) base = ld_acq(&g_cnt[0]);

    // ---- one-time weight gather (column slices, gate-major local order) ----
    for (int idx = tid; idx < SM_WX; idx += NTHR) {
        int k = idx >> 5, lc = idx & 31;
        int gate = lc >> 3, unit = lc & 7;
        Wx_s[idx] = Wx[(size_t)k * G4_ + gate * H_ + u0 + unit];
    }
    for (int idx = tid; idx < SM_WH; idx += NTHR) {
        int k = idx >> 5, lc = idx & 31;
        int gate = lc >> 3, unit = lc & 7;
        Wh_s[idx] = Wh[(size_t)k * G4_ + gate * H_ + u0 + unit];
    }
    if (tid < NC) {
        int gate = tid >> 3, unit = tid & 7;
        b_sh[tid] = bias[gate * H_ + u0 + unit];
    }
    for (int idx = tid; idx < SM_C; idx += NTHR) c_sh[idx] = 0.f;
    __syncthreads();

    // compute-role mapping: 4x4 tile per thread
    const int lc0  = (wtid >> 4) * 4;   // col quad: 8 x 4 = 32 cols
    const int bat0 = (wtid & 15) * 4;   // batch quad: 16 x 4 = 64 batches

    const int bat  = wtid >> 1;         // staging role: batch 0..63
    const int half = wtid & 1;          // staging role: k-half

    float* awg   = a_sh + wg * (2 * KC * B_);
    float* zwg   = z_sh + wg * SM_Z1;
    const int barid = wg + 1;
    const int xc0 = wg * XCW;
    const int hc0 = wg * HCW;

    for (int t = 0; t < T_; ++t) {
        unsigned long long acc[4][2];
        #pragma unroll
        for (int c = 0; c < 4; ++c) { acc[c][0] = 0ull; acc[c][1] = 0ull; }

        // ---------- phase X: XCW chunks of x_t (no dependence on h) ----------
        const float* xb = x + (size_t)bat * (T_ * DIN_) + (size_t)t * DIN_;
        stage16(xb + xc0 * KC, awg + bat, half);
        BARW(barid);
        for (int j = 0; j < XCW; ++j) {
            int cur = j & 1;
            if (j < XCW - 1)
                stage16(xb + (xc0 + j + 1) * KC, awg + (cur ^ 1) * KC * B_ + bat, half);
            compute16(Wx_s + (xc0 + j) * KC * NC, awg + cur * KC * B_, acc, lc0, bat0);
            BARW(barid);
        }

        // ---------- phase H: wait for h_{t-1}, then HCW chunks ----------
        if (t > 0) {
            if (tid == 0) {
                while (ld_acq(&g_cnt[t - 1]) < base + NCTA) { __nanosleep(32); }
            }
            __syncthreads();
            const float* hb = g_hs + (size_t)(t - 1) * (B_ * H_) + (size_t)bat * H_;
            stage16(hb + hc0 * KC, awg + bat, half);
            BARW(barid);
            for (int j = 0; j < HCW; ++j) {
                int cur = j & 1;
                if (j < HCW - 1)
                    stage16(hb + (hc0 + j + 1) * KC, awg + (cur ^ 1) * KC * B_ + bat, half);
                compute16(Wh_s + (hc0 + j) * KC * NC, awg + cur * KC * B_, acc, lc0, bat0);
                BARW(barid);
            }
        }

        // ---------- publish partial z to this wg's buffer ----------
        #pragma unroll
        for (int c = 0; c < 4; ++c) {
            ulonglong2 v; v.x = acc[c][0]; v.y = acc[c][1];
            *(ulonglong2*)(zwg + (lc0 + c) * B_ + bat0) = v;
        }
        __syncthreads();

        // ---------- cell update: 512 cells, 1 per thread ----------
        {
            int cb   = tid >> 3;         // batch
            int unit = tid & 7;
            float zg4[4];
            #pragma unroll
            for (int g = 0; g < 4; ++g) {
                int row = (g * NU + unit) * B_ + cb;
                float s = b_sh[g * NU + unit];
                #pragma unroll
                for (int w = 0; w < NWG; ++w) s += z_sh[w * SM_Z1 + row];
                zg4[g] = s;
            }
            float ig = 1.f / (1.f + expf(-zg4[0]));
            float fg = 1.f / (1.f + expf(-zg4[1]));
            float gg = tanhf(zg4[2]);
            float og = 1.f / (1.f + expf(-zg4[3]));
            float cv = fg * c_sh[tid] + ig * gg;
            c_sh[tid] = cv;
            g_hs[(size_t)t * (B_ * H_) + (size_t)cb * H_ + u0 + unit] = og * tanhf(cv);
        }

        // ---------- release h_t ----------
        __threadfence();
        __syncthreads();
        if (tid == 0) atomicAdd(&g_cnt[t], 1);
    }

    // ==================== projection phase: relu(hs @ Wo + bo) ====================
    // CTA i projects timesteps 4i .. 4i+3.
    const int t0p = blockIdx.x * 4;
    if (tid == 0) {
        for (int tt = 0; tt < 4; ++tt)
            while (ld_acq(&g_cnt[t0p + tt]) < base + NCTA) { __nanosleep(32); }
    }
    __syncthreads();

    float* Bsh = sm;                       // reuse SMEM: [32][DOUT_] = 32 KB
    const int bb = tid >> 3;               // batch 0..63
    const int nq = (tid & 7) * 4;          // col sub-offset; thread covers nq+32*j, j=0..7

    for (int tt = 0; tt < 4; ++tt) {
        const int t = t0p + tt;
        const float* A = g_hs + (size_t)t * (B_ * H_) + (size_t)bb * H_;
        unsigned long long acc2[8][2];
        #pragma unroll
        for (int j = 0; j < 8; ++j) { acc2[j][0] = 0ull; acc2[j][1] = 0ull; }

        for (int k0 = 0; k0 < H_; k0 += 32) {
            // stage Wo[k0:k0+32, :] into Bsh (coalesced, 16 floats/thread)
            {
                int kk = tid >> 4, n0s = (tid & 15) * 16;
                const float4* wsrc = (const float4*)(Wo + (size_t)(k0 + kk) * DOUT_ + n0s);
                float4* wdst = (float4*)(Bsh + kk * DOUT_ + n0s);
                #pragma unroll
                for (int q = 0; q < 4; ++q) wdst[q] = __ldcg(wsrc + q);
            }
            __syncthreads();

            float4 a4[8];
            const float4* ap = (const float4*)(A + k0);
            #pragma unroll
            for (int q = 0; q < 8; ++q) a4[q] = ap[q];

            #pragma unroll
            for (int kk = 0; kk < 32; ++kk) {
                float av = ((const float*)a4)[kk];
                unsigned long long aa = pack2(av, av);
                const float* wr = Bsh + kk * DOUT_ + nq;
                #pragma unroll
                for (int j = 0; j < 8; ++j) {
                    ulonglong2 w2 = *(const ulonglong2*)(wr + 32 * j);   // conflict-free
                    acc2[j][0] = fma2(w2.x, aa, acc2[j][0]);
                    acc2[j][1] = fma2(w2.y, aa, acc2[j][1]);
                }
            }
            __syncthreads();
        }

        float* orow = out + (size_t)bb * (T_ * DOUT_) + (size_t)t * DOUT_;
        #pragma unroll
        for (int j = 0; j < 8; ++j) {
            int n = nq + 32 * j;
            float o0, o1, o2, o3;
            unpack2(acc2[j][0], o0, o1);
            unpack2(acc2[j][1], o2, o3);
            float4 r;
            r.x = fmaxf(o0 + bo[n + 0], 0.f);
            r.y = fmaxf(o1 + bo[n + 1], 0.f);
            r.z = fmaxf(o2 + bo[n + 2], 0.f);
            r.w = fmaxf(o3 + bo[n + 3], 0.f);
            *(float4*)(orow + n) = r;
        }
    }
}

extern "C" void kernel_launch(void* const* d_in, const int* in_sizes, int n_in,
                              void* d_out, int out_size) {
    const float* x  = (const float*)d_in[0];
    const float* Wx = (const float*)d_in[1];
    const float* Wh = (const float*)d_in[2];
    const float* b  = (const float*)d_in[3];
    const float* Wo = (const float*)d_in[4];
    const float* bo = (const float*)d_in[5];
    float* out = (float*)d_out;

    cudaFuncSetAttribute(mega_kernel, cudaFuncAttributeMaxDynamicSharedMemorySize,
                         SMEM_BYTES);
    mega_kernel<<<NCTA, NTHR, SMEM_BYTES>>>(x, Wx, Wh, b, Wo, bo, out);
}

// round 15
// speedup vs baseline: 2.1752x; 1.5243x over previous
#include <cuda_runtime.h>

// ---------------- problem constants ----------------
#define T_    512
#define B_    64
#define DIN_  256
#define H_    1024
#define G4_   4096
#define DOUT_ 256

// ---------------- tiling ----------------
#define NCTA  128          // CTAs; each owns NU hidden units
#define NU    8            // hidden units per CTA
#define NC    32           // gate columns per CTA (4 gates x NU)
#define NTHR  256          // 8 warps; each warp owns a k-slice
#define NWARP 8
#define XKW   (DIN_/NWARP) // 32 x-k per warp
#define HKW   (H_/NWARP)   // 128 h-k per warp

// SMEM layout (floats)
#define SM_WX (DIN_*NC)        // 8192
#define SM_WH (H_*NC)          // 32768
#define SM_Z  (NWARP*16*B_*2)  // 16384  (per-warp partial z, 64-bit cells)
#define SM_C  (B_*NU)          // 512
#define SM_B  (NC)             // 32
#define SMEM_FLOATS (SM_WX+SM_WH+SM_Z+SM_C+SM_B)
#define SMEM_BYTES  (SMEM_FLOATS*4)   // 231,552 B

// ---------------- device scratch (static; no runtime allocation) ----------------
__device__ float g_hs[(size_t)T_*H_*B_];    // [t][h][b]  transposed! (128 MB)
__device__ float g_xT[(size_t)T_*DIN_*B_];  // [t][d][b]  transposed x (134 MB)
__device__ int   g_cnt[T_];                 // monotonic per-step counters
__device__ int   g_xflag[NCTA];             // transpose-done flags (monotonic)

// ---------------- f32x2 helpers ----------------
static __device__ __forceinline__ unsigned long long pack2(float lo, float hi) {
    unsigned long long r;
    asm("mov.b64 %0, {%1, %2};" : "=l"(r) : "f"(lo), "f"(hi));
    return r;
}
static __device__ __forceinline__ unsigned long long fma2(unsigned long long a,
                                                          unsigned long long b,
                                                          unsigned long long c) {
    unsigned long long d;
    asm("fma.rn.f32x2 %0, %1, %2, %3;" : "=l"(d) : "l"(a), "l"(b), "l"(c));
    return d;
}
static __device__ __forceinline__ void unpack2(unsigned long long v, float &lo, float &hi) {
    asm("mov.b64 {%0, %1}, %2;" : "=f"(lo), "=f"(hi) : "l"(v));
}
static __device__ __forceinline__ int ld_acq(const int* p) {
    int v;
    asm volatile("ld.acquire.gpu.s32 %0, [%1];" : "=r"(v) : "l"(p) : "memory");
    return v;
}
static __device__ __forceinline__ void st_rel(int* p, int v) {
    asm volatile("st.release.gpu.s32 [%0], %1;" :: "l"(p), "r"(v) : "memory");
}

// One k of the recurrence GEMM. wrow: SMEM weight row (+colbase);
// arow: GLOBAL activation row (+batbase). acc[cp][b] covers 8 cols x 8 bats.
static __device__ __forceinline__ void kstep(const float* __restrict__ wrow,
                                             const float* __restrict__ arow,
                                             unsigned long long acc[4][8]) {
    ulonglong2 wA = *(const ulonglong2*)(wrow);       // cols c0c1, c2c3 (pre-packed)
    ulonglong2 wB = *(const ulonglong2*)(wrow + 4);   // cols c4c5, c6c7
    float4 a0 = __ldcg((const float4*)(arow));        // bats +0..3 (L2)
    float4 a1 = __ldcg((const float4*)(arow + 4));    // bats +4..7
    float af[8] = {a0.x, a0.y, a0.z, a0.w, a1.x, a1.y, a1.z, a1.w};
    #pragma unroll
    for (int b = 0; b < 8; ++b) {
        unsigned long long ab = pack2(af[b], af[b]);
        acc[0][b] = fma2(wA.x, ab, acc[0][b]);
        acc[1][b] = fma2(wA.y, ab, acc[1][b]);
        acc[2][b] = fma2(wB.x, ab, acc[2][b]);
        acc[3][b] = fma2(wB.y, ab, acc[3][b]);
    }
}

// ==================== megakernel: transpose -> scan -> projection ====================
__global__ void __launch_bounds__(NTHR, 1)
mega_kernel(const float* __restrict__ x, const float* __restrict__ Wx,
            const float* __restrict__ Wh, const float* __restrict__ bias,
            const float* __restrict__ Wo, const float* __restrict__ bo,
            float* __restrict__ out) {
    extern __shared__ float sm[];
    float* Wx_s = sm;                 // [DIN_][NC]
    float* Wh_s = Wx_s + SM_WX;       // [H_][NC]
    float* z_sh = Wh_s + SM_WH;       // [w][cpg(16)][B_][2]
    float* c_sh = z_sh + SM_Z;        // [u*64 + b]
    float* b_sh = c_sh + SM_C;        // [NC]

    const int tid  = threadIdx.x;
    const int cta  = blockIdx.x;
    const int u0   = cta * NU;

    // epoch base: every thread reads BEFORE any CTA can increment (first
    // increment happens after the transpose flag exchange below).
    const int base = ld_acq(&g_cnt[0]);
    const int rep1 = base / NCTA + 1;

    // ---------- phase 0: transpose x[b][t][d] -> g_xT[t][d][b] (4 t's per CTA) ----------
    {
        const int t0x = cta * 4;
        for (int tt = 0; tt < 4; ++tt) {
            const int t = t0x + tt;
            for (int id = tid; id < 1024; id += NTHR) {
                int dq = id >> 4, bq = id & 15;
                const float* xs = x + (size_t)(bq * 4) * (T_ * DIN_) + (size_t)t * DIN_ + dq * 4;
                float4 r0 = __ldcs((const float4*)(xs));
                float4 r1 = __ldcs((const float4*)(xs + T_ * DIN_));
                float4 r2 = __ldcs((const float4*)(xs + 2 * T_ * DIN_));
                float4 r3 = __ldcs((const float4*)(xs + 3 * T_ * DIN_));
                float* xd = g_xT + (size_t)t * (DIN_ * B_) + (size_t)(dq * 4) * B_ + bq * 4;
                *(float4*)(xd)          = make_float4(r0.x, r1.x, r2.x, r3.x);
                *(float4*)(xd + B_)     = make_float4(r0.y, r1.y, r2.y, r3.y);
                *(float4*)(xd + 2 * B_) = make_float4(r0.z, r1.z, r2.z, r3.z);
                *(float4*)(xd + 3 * B_) = make_float4(r0.w, r1.w, r2.w, r3.w);
            }
        }
        __threadfence();
        __syncthreads();
        if (tid == 0) st_rel(&g_xflag[cta], rep1);
    }

    // ---------- one-time weight gather into SMEM (overlaps peers' transposes) ----------
    for (int idx = tid; idx < SM_WX; idx += NTHR) {
        int k = idx >> 5, lc = idx & 31;
        int gate = lc >> 3, unit = lc & 7;
        Wx_s[idx] = Wx[(size_t)k * G4_ + gate * H_ + u0 + unit];
    }
    for (int idx = tid; idx < SM_WH; idx += NTHR) {
        int k = idx >> 5, lc = idx & 31;
        int gate = lc >> 3, unit = lc & 7;
        Wh_s[idx] = Wh[(size_t)k * G4_ + gate * H_ + u0 + unit];
    }
    if (tid < NC) {
        int gate = tid >> 3, unit = tid & 7;
        b_sh[tid] = bias[gate * H_ + u0 + unit];
    }
    for (int idx = tid; idx < SM_C; idx += NTHR) c_sh[idx] = 0.f;

    // wait for ALL transposes (each thread polls one flag)
    if (tid < NCTA) {
        while (ld_acq(&g_xflag[tid]) < rep1) { __nanosleep(64); }
    }
    __syncthreads();

    // ---------- scan phase ----------
    const int w    = tid >> 5;            // warp 0..7 = k-slice owner
    const int lane = tid & 31;
    const int cq   = lane >> 3;           // 0..3 -> cols cq*8..+7
    const int bq   = lane & 7;            // 0..7 -> bats bq*8..+7
    const int colbase = cq * 8;
    const int batbase = bq * 8;
    const int xk0 = w * XKW;
    const int hk0 = w * HKW;

    const float* wpx = Wx_s + xk0 * NC + colbase;
    const float* wph = Wh_s + hk0 * NC + colbase;

    // cell-update mapping: 2 cells per thread, cell = u*64 + b
    const int cu  = tid >> 5;             // unit 0..7
    const int cb0 = (tid & 31) * 2;       // batch 0,2,..,62

    for (int t = 0; t < T_; ++t) {
        unsigned long long acc[4][8];
        #pragma unroll
        for (int cp = 0; cp < 4; ++cp)
            #pragma unroll
            for (int b = 0; b < 8; ++b) acc[cp][b] = 0ull;

        // --- x part (no dependence on h; warp-autonomous) ---
        {
            const float* ap = g_xT + (size_t)t * (DIN_ * B_) + xk0 * B_ + batbase;
            #pragma unroll 8
            for (int kk = 0; kk < XKW; ++kk)
                kstep(wpx + kk * NC, ap + kk * B_, acc);
        }

        // --- h part: per-warp flag wait, then 128 k ---
        if (t > 0) {
            if (lane == 0) {
                while (ld_acq(&g_cnt[t - 1]) < base + NCTA) { __nanosleep(32); }
            }
            __syncwarp();
            const float* ap = g_hs + (size_t)(t - 1) * (H_ * B_) + hk0 * B_ + batbase;
            #pragma unroll 8
            for (int kk = 0; kk < HKW; ++kk)
                kstep(wph + kk * NC, ap + kk * B_, acc);
        }

        // --- publish partial z (64-bit cells: [w][cpg][bat][2]) ---
        #pragma unroll
        for (int cp = 0; cp < 4; ++cp)
            #pragma unroll
            for (int b = 0; b < 8; ++b)
                *(unsigned long long*)(z_sh + (size_t)(((w * 16) + (cq * 4) + cp) * B_
                                                       + batbase + b) * 2) = acc[cp][b];
        __syncthreads();

        // --- cell update: 2 cells per thread ---
        {
            float hout[2];
            #pragma unroll
            for (int i = 0; i < 2; ++i) {
                int b = cb0 + i;
                float zg[4];
                #pragma unroll
                for (int g = 0; g < 4; ++g) {
                    int col = g * 8 + cu;
                    int cpg = col >> 1, par = col & 1;
                    float s = b_sh[col];
                    #pragma unroll
                    for (int ww = 0; ww < NWARP; ++ww)
                        s += z_sh[((ww * 16 + cpg) * B_ + b) * 2 + par];
                    zg[g] = s;
                }
                float ig = 1.f / (1.f + expf(-zg[0]));
                float fg = 1.f / (1.f + expf(-zg[1]));
                float gg = tanhf(zg[2]);
                float og = 1.f / (1.f + expf(-zg[3]));
                float cv = fg * c_sh[cu * B_ + b] + ig * gg;
                c_sh[cu * B_ + b] = cv;
                hout[i] = og * tanhf(cv);
            }
            *(float2*)(g_hs + (size_t)t * (H_ * B_) + (size_t)(u0 + cu) * B_ + cb0)
                = make_float2(hout[0], hout[1]);
        }

        // --- release h_t ---
        __threadfence();
        __syncthreads();
        if (tid == 0) atomicAdd(&g_cnt[t], 1);
    }

    // ---------- projection phase: relu(hs @ Wo + bo); CTA i does t = 4i..4i+3 ----------
    const int t0p = cta * 4;
    if (tid < 4) {
        while (ld_acq(&g_cnt[t0p + tid]) < base + NCTA) { __nanosleep(64); }
    }
    __syncthreads();

    float* h_sh  = sm;            // [32][B_]   = 2048 floats (overlay)
    float* Wo_sh = sm + 2048;     // [32][DOUT_] = 8192 floats

    const int bb = tid >> 2;            // batch 0..63
    const int nq = (tid & 3) * 4;       // col sub-offset; covers nq + 16*j

    for (int tt = 0; tt < 4; ++tt) {
        const int t = t0p + tt;
        unsigned long long acc2[16][2];
        #pragma unroll
        for (int j = 0; j < 16; ++j) { acc2[j][0] = 0ull; acc2[j][1] = 0ull; }

        for (int k0 = 0; k0 < H_; k0 += 32) {
            const float* hsrc = g_hs + (size_t)t * (H_ * B_) + (size_t)k0 * B_;
            #pragma unroll
            for (int q = 0; q < 2; ++q)
                *(float4*)(h_sh + tid * 8 + q * 4) =
                    __ldcg((const float4*)(hsrc + tid * 8 + q * 4));
            const float* wsrc = Wo + (size_t)k0 * DOUT_;
            #pragma unroll
            for (int q = 0; q < 8; ++q)
                *(float4*)(Wo_sh + tid * 32 + q * 4) =
                    __ldcg((const float4*)(wsrc + tid * 32 + q * 4));
            __syncthreads();

            #pragma unroll 8
            for (int kk = 0; kk < 32; ++kk) {
                float av = h_sh[kk * B_ + bb];
                unsigned long long aa = pack2(av, av);
                const float* wr = Wo_sh + kk * DOUT_ + nq;
                #pragma unroll
                for (int j = 0; j < 16; ++j) {
                    ulonglong2 w2 = *(const ulonglong2*)(wr + 16 * j);
                    acc2[j][0] = fma2(w2.x, aa, acc2[j][0]);
                    acc2[j][1] = fma2(w2.y, aa, acc2[j][1]);
                }
            }
            __syncthreads();
        }

        float* orow = out + (size_t)bb * (T_ * DOUT_) + (size_t)t * DOUT_;
        #pragma unroll
        for (int j = 0; j < 16; ++j) {
            int n = nq + 16 * j;
            float o0, o1, o2, o3;
            unpack2(acc2[j][0], o0, o1);
            unpack2(acc2[j][1], o2, o3);
            float4 r;
            r.x = fmaxf(o0 + bo[n + 0], 0.f);
            r.y = fmaxf(o1 + bo[n + 1], 0.f);
            r.z = fmaxf(o2 + bo[n + 2], 0.f);
            r.w = fmaxf(o3 + bo[n + 3], 0.f);
            *(float4*)(orow + n) = r;
        }
    }
}

extern "C" void kernel_launch(void* const* d_in, const int* in_sizes, int n_in,
                              void* d_out, int out_size) {
    const float* x  = (const float*)d_in[0];
    const float* Wx = (const float*)d_in[1];
    const float* Wh = (const float*)d_in[2];
    const float* b  = (const float*)d_in[3];
    const float* Wo = (const float*)d_in[4];
    const float* bo = (const float*)d_in[5];
    float* out = (float*)d_out;

    cudaFuncSetAttribute(mega_kernel, cudaFuncAttributeMaxDynamicSharedMemorySize,
                         SMEM_BYTES);
    mega_kernel<<<NCTA, NTHR, SMEM_BYTES>>>(x, Wx, Wh, b, Wo, bo, out);
}

// round 16
// speedup vs baseline: 2.2841x; 1.0501x over previous
#include <cuda_runtime.h>

// ---------------- problem constants ----------------
#define T_    512
#define B_    64
#define DIN_  256
#define H_    1024
#define G4_   4096
#define DOUT_ 256

// ---------------- tiling ----------------
#define NCTA  128          // CTAs; each owns NU hidden units
#define NU    8            // hidden units per CTA
#define NC    32           // gate columns per CTA (4 gates x NU)
#define NTHR  512          // 16 warps = 8 k-groups x 2 batch-halves
#define NGRP  8
#define XKG   (DIN_/NGRP)  // 32 x-k per group
#define HKG   (H_/NGRP)    // 128 h-k per group

// SMEM layout (floats)
#define SM_WX (DIN_*NC)        // 8192
#define SM_WH (H_*NC)          // 32768
#define SM_Z  (NGRP*16*B_*2)   // 16384  (per-group partial z, 64-bit cells)
#define SM_C  (B_*NU)          // 512
#define SM_B  (NC)             // 32
#define SMEM_FLOATS (SM_WX+SM_WH+SM_Z+SM_C+SM_B)
#define SMEM_BYTES  (SMEM_FLOATS*4)   // 231,552 B

// ---------------- device scratch (static; no runtime allocation) ----------------
__device__ float g_hs[(size_t)T_*H_*B_];    // [t][h][b]  transposed (128 MB)
__device__ float g_xT[(size_t)T_*DIN_*B_];  // [t][d][b]  transposed x
__device__ int   g_cnt[T_];                 // monotonic per-step counters
__device__ int   g_xflag[NCTA];             // transpose-done flags (monotonic)

// ---------------- f32x2 helpers ----------------
static __device__ __forceinline__ unsigned long long pack2(float lo, float hi) {
    unsigned long long r;
    asm("mov.b64 %0, {%1, %2};" : "=l"(r) : "f"(lo), "f"(hi));
    return r;
}
static __device__ __forceinline__ unsigned long long fma2(unsigned long long a,
                                                          unsigned long long b,
                                                          unsigned long long c) {
    unsigned long long d;
    asm("fma.rn.f32x2 %0, %1, %2, %3;" : "=l"(d) : "l"(a), "l"(b), "l"(c));
    return d;
}
static __device__ __forceinline__ void unpack2(unsigned long long v, float &lo, float &hi) {
    asm("mov.b64 {%0, %1}, %2;" : "=f"(lo), "=f"(hi) : "l"(v));
}
static __device__ __forceinline__ int ld_acq(const int* p) {
    int v;
    asm volatile("ld.acquire.gpu.s32 %0, [%1];" : "=r"(v) : "l"(p) : "memory");
    return v;
}
static __device__ __forceinline__ void st_rel(int* p, int v) {
    asm volatile("st.release.gpu.s32 [%0], %1;" :: "l"(p), "r"(v) : "memory");
}

// One k of the recurrence GEMM. wrow: SMEM weight row (+colbase), 8 cols as
// 4 pre-packed f32x2 col-pairs; arow: GLOBAL activation row (+batbase), 4 bats.
// acc[cp][b]: col-pair cp (2 cols), bat b.  16 FFMA2 per call.
static __device__ __forceinline__ void kstep(const float* __restrict__ wrow,
                                             const float* __restrict__ arow,
                                             unsigned long long acc[4][4]) {
    ulonglong2 wA = *(const ulonglong2*)(wrow);       // col-pairs 0,1
    ulonglong2 wB = *(const ulonglong2*)(wrow + 4);   // col-pairs 2,3
    float4 a = __ldcg((const float4*)(arow));         // 4 bats from L2
    unsigned long long ab[4] = {pack2(a.x, a.x), pack2(a.y, a.y),
                                pack2(a.z, a.z), pack2(a.w, a.w)};
    #pragma unroll
    for (int b = 0; b < 4; ++b) {
        acc[0][b] = fma2(wA.x, ab[b], acc[0][b]);
        acc[1][b] = fma2(wA.y, ab[b], acc[1][b]);
        acc[2][b] = fma2(wB.x, ab[b], acc[2][b]);
        acc[3][b] = fma2(wB.y, ab[b], acc[3][b]);
    }
}

// ==================== megakernel: transpose -> scan -> projection ====================
__global__ void __launch_bounds__(NTHR, 1)
mega_kernel(const float* __restrict__ x, const float* __restrict__ Wx,
            const float* __restrict__ Wh, const float* __restrict__ bias,
            const float* __restrict__ Wo, const float* __restrict__ bo,
            float* __restrict__ out) {
    extern __shared__ float sm[];
    float* Wx_s = sm;                 // [DIN_][NC]
    float* Wh_s = Wx_s + SM_WX;       // [H_][NC]
    float* z_sh = Wh_s + SM_WH;       // [grp][cpg(16)][B_][2]
    float* c_sh = z_sh + SM_Z;        // [u*64 + b]
    float* b_sh = c_sh + SM_C;        // [NC]

    const int tid  = threadIdx.x;
    const int cta  = blockIdx.x;
    const int u0   = cta * NU;

    // epoch base: read BEFORE any CTA can increment this launch.
    const int base = ld_acq(&g_cnt[0]);
    const int rep1 = base / NCTA + 1;

    // ---------- phase 0: transpose x[b][t][d] -> g_xT[t][d][b] (4 t's per CTA) ----------
    {
        const int t0x = cta * 4;
        for (int tt = 0; tt < 4; ++tt) {
            const int t = t0x + tt;
            for (int id = tid; id < 1024; id += NTHR) {
                int dq = id >> 4, bq = id & 15;
                const float* xs = x + (size_t)(bq * 4) * (T_ * DIN_) + (size_t)t * DIN_ + dq * 4;
                float4 r0 = __ldcs((const float4*)(xs));
                float4 r1 = __ldcs((const float4*)(xs + T_ * DIN_));
                float4 r2 = __ldcs((const float4*)(xs + 2 * T_ * DIN_));
                float4 r3 = __ldcs((const float4*)(xs + 3 * T_ * DIN_));
                float* xd = g_xT + (size_t)t * (DIN_ * B_) + (size_t)(dq * 4) * B_ + bq * 4;
                *(float4*)(xd)          = make_float4(r0.x, r1.x, r2.x, r3.x);
                *(float4*)(xd + B_)     = make_float4(r0.y, r1.y, r2.y, r3.y);
                *(float4*)(xd + 2 * B_) = make_float4(r0.z, r1.z, r2.z, r3.z);
                *(float4*)(xd + 3 * B_) = make_float4(r0.w, r1.w, r2.w, r3.w);
            }
        }
        __threadfence();
        __syncthreads();
        if (tid == 0) st_rel(&g_xflag[cta], rep1);
    }

    // ---------- one-time weight gather into SMEM ----------
    for (int idx = tid; idx < SM_WX; idx += NTHR) {
        int k = idx >> 5, lc = idx & 31;
        int gate = lc >> 3, unit = lc & 7;
        Wx_s[idx] = Wx[(size_t)k * G4_ + gate * H_ + u0 + unit];
    }
    for (int idx = tid; idx < SM_WH; idx += NTHR) {
        int k = idx >> 5, lc = idx & 31;
        int gate = lc >> 3, unit = lc & 7;
        Wh_s[idx] = Wh[(size_t)k * G4_ + gate * H_ + u0 + unit];
    }
    if (tid < NC) {
        int gate = tid >> 3, unit = tid & 7;
        b_sh[tid] = bias[gate * H_ + u0 + unit];
    }
    for (int idx = tid; idx < SM_C; idx += NTHR) c_sh[idx] = 0.f;

    // wait for ALL transposes
    if (tid < NCTA) {
        while (ld_acq(&g_xflag[tid]) < rep1) { __nanosleep(64); }
    }
    __syncthreads();

    // ---------- scan phase ----------
    const int w    = tid >> 5;            // warp 0..15
    const int grp  = w >> 1;              // k-group 0..7
    const int half = w & 1;               // batch half
    const int lane = tid & 31;
    const int cq   = lane >> 3;           // 0..3 -> col-pairs cq*4..+3 (cols cq*8..+7)
    const int colbase = cq * 8;
    const int batbase = half * 32 + (lane & 7) * 4;   // 4 bats per thread
    const int xk0 = grp * XKG;
    const int hk0 = grp * HKG;

    const float* wpx = Wx_s + xk0 * NC + colbase;
    const float* wph = Wh_s + hk0 * NC + colbase;

    // cell-update mapping: 1 cell per thread
    const int cu = tid >> 6;              // unit 0..7
    const int cb = tid & 63;              // batch 0..63

    for (int t = 0; t < T_; ++t) {
        unsigned long long acc[4][4];
        #pragma unroll
        for (int cp = 0; cp < 4; ++cp)
            #pragma unroll
            for (int b = 0; b < 4; ++b) acc[cp][b] = 0ull;

        // --- x part (no dependence on h; warp-autonomous) ---
        {
            const float* ap = g_xT + (size_t)t * (DIN_ * B_) + xk0 * B_ + batbase;
            #pragma unroll 4
            for (int kk = 0; kk < XKG; ++kk)
                kstep(wpx + kk * NC, ap + kk * B_, acc);
        }

        // --- h part: per-warp flag wait, then HKG k ---
        if (t > 0) {
            if (lane == 0) {
                while (ld_acq(&g_cnt[t - 1]) < base + NCTA) { __nanosleep(32); }
            }
            __syncwarp();
            const float* ap = g_hs + (size_t)(t - 1) * (H_ * B_) + hk0 * B_ + batbase;
            #pragma unroll 4
            for (int kk = 0; kk < HKG; ++kk)
                kstep(wph + kk * NC, ap + kk * B_, acc);
        }

        // --- publish partial z (64-bit cells: [grp][cpg][bat][2]) ---
        #pragma unroll
        for (int cp = 0; cp < 4; ++cp)
            #pragma unroll
            for (int b = 0; b < 4; ++b)
                *(unsigned long long*)(z_sh + (size_t)((grp * 16 + cq * 4 + cp) * B_
                                                       + batbase + b) * 2) = acc[cp][b];
        __syncthreads();

        // --- cell update: 512 cells, 1 per thread ---
        {
            float zg[4];
            #pragma unroll
            for (int g = 0; g < 4; ++g) {
                int col = g * 8 + cu;
                int cpg = col >> 1, par = col & 1;
                float s = b_sh[col];
                #pragma unroll
                for (int gg2 = 0; gg2 < NGRP; ++gg2)
                    s += z_sh[((gg2 * 16 + cpg) * B_ + cb) * 2 + par];
                zg[g] = s;
            }
            float ig = 1.f / (1.f + expf(-zg[0]));
            float fg = 1.f / (1.f + expf(-zg[1]));
            float gv = tanhf(zg[2]);
            float og = 1.f / (1.f + expf(-zg[3]));
            float cv = fg * c_sh[cu * B_ + cb] + ig * gv;
            c_sh[cu * B_ + cb] = cv;
            g_hs[(size_t)t * (H_ * B_) + (size_t)(u0 + cu) * B_ + cb] = og * tanhf(cv);
        }

        // --- release h_t ---
        __threadfence();
        __syncthreads();
        if (tid == 0) atomicAdd(&g_cnt[t], 1);
    }

    // ---------- projection phase: relu(hs @ Wo + bo); CTA i does t = 4i..4i+3 ----------
    const int t0p = cta * 4;
    if (tid < 4) {
        while (ld_acq(&g_cnt[t0p + tid]) < base + NCTA) { __nanosleep(64); }
    }
    __syncthreads();

    float* h_sh  = sm;            // [32][B_]    = 2048 floats (overlay)
    float* Wo_sh = sm + 2048;     // [32][DOUT_] = 8192 floats

    const int bb = tid >> 3;            // batch 0..63
    const int nq = (tid & 7) * 4;       // col sub-offset; covers nq + 32*j, j=0..7

    for (int tt = 0; tt < 4; ++tt) {
        const int t = t0p + tt;
        unsigned long long acc2[8][2];
        #pragma unroll
        for (int j = 0; j < 8; ++j) { acc2[j][0] = 0ull; acc2[j][1] = 0ull; }

        for (int k0 = 0; k0 < H_; k0 += 32) {
            const float* hsrc = g_hs + (size_t)t * (H_ * B_) + (size_t)k0 * B_;
            *(float4*)(h_sh + tid * 4) = __ldcg((const float4*)(hsrc + tid * 4));
            const float* wsrc = Wo + (size_t)k0 * DOUT_;
            #pragma unroll
            for (int q = 0; q < 4; ++q)
                *(float4*)(Wo_sh + tid * 16 + q * 4) =
                    __ldcg((const float4*)(wsrc + tid * 16 + q * 4));
            __syncthreads();

            #pragma unroll 8
            for (int kk = 0; kk < 32; ++kk) {
                float av = h_sh[kk * B_ + bb];
                unsigned long long aa = pack2(av, av);
                const float* wr = Wo_sh + kk * DOUT_ + nq;
                #pragma unroll
                for (int j = 0; j < 8; ++j) {
                    ulonglong2 w2 = *(const ulonglong2*)(wr + 32 * j);
                    acc2[j][0] = fma2(w2.x, aa, acc2[j][0]);
                    acc2[j][1] = fma2(w2.y, aa, acc2[j][1]);
                }
            }
            __syncthreads();
        }

        float* orow = out + (size_t)bb * (T_ * DOUT_) + (size_t)t * DOUT_;
        #pragma unroll
        for (int j = 0; j < 8; ++j) {
            int n = nq + 32 * j;
            float o0, o1, o2, o3;
            unpack2(acc2[j][0], o0, o1);
            unpack2(acc2[j][1], o2, o3);
            float4 r;
            r.x = fmaxf(o0 + bo[n + 0], 0.f);
            r.y = fmaxf(o1 + bo[n + 1], 0.f);
            r.z = fmaxf(o2 + bo[n + 2], 0.f);
            r.w = fmaxf(o3 + bo[n + 3], 0.f);
            *(float4*)(orow + n) = r;
        }
    }
}

extern "C" void kernel_launch(void* const* d_in, const int* in_sizes, int n_in,
                              void* d_out, int out_size) {
    const float* x  = (const float*)d_in[0];
    const float* Wx = (const float*)d_in[1];
    const float* Wh = (const float*)d_in[2];
    const float* b  = (const float*)d_in[3];
    const float* Wo = (const float*)d_in[4];
    const float* bo = (const float*)d_in[5];
    float* out = (float*)d_out;

    cudaFuncSetAttribute(mega_kernel, cudaFuncAttributeMaxDynamicSharedMemorySize,
                         SMEM_BYTES);
    mega_kernel<<<NCTA, NTHR, SMEM_BYTES>>>(x, Wx, Wh, b, Wo, bo, out);
}